// round 8
// baseline (speedup 1.0000x reference)
#include <cuda_runtime.h>
#include <cuda_bf16.h>
#include <math.h>
#include <stdint.h>

#define Bb_ 64
#define Tt_ 4096
#define Dd_ 256
#define Hh_ 256
#define Oo_ 256

// Scratch (device globals: no allocation allowed in kernel_launch)
__device__ float g_xp[(size_t)Tt_ * Bb_ * Hh_];   // (T, B, H)
__device__ float g_hs[(size_t)Bb_ * Tt_ * Hh_];   // (B, T, H)
// W split into bf16 hi/lo, stored TRANSPOSED: [n][k]
__device__ __nv_bfloat16 g_wxh_hi[256 * 256];
__device__ __nv_bfloat16 g_wxh_lo[256 * 256];
__device__ __nv_bfloat16 g_why_hi[256 * 256];
__device__ __nv_bfloat16 g_why_lo[256 * 256];

// ---------------------------------------------------------------------------
// helpers
// ---------------------------------------------------------------------------
__device__ __forceinline__ uint32_t smem_u32(const void* p) {
    uint32_t a;
    asm("{ .reg .u64 t; cvta.to.shared.u64 t, %1; cvt.u32.u64 %0, t; }"
        : "=r"(a) : "l"(p));
    return a;
}
__device__ __forceinline__ void mbar_init(uint32_t addr, uint32_t cnt) {
    asm volatile("mbarrier.init.shared.b64 [%0], %1;" :: "r"(addr), "r"(cnt) : "memory");
}

// ---------------------------------------------------------------------------
// Weight split kernel: W (K=256,N=256) fp32 -> transposed bf16 hi/lo [n][k]
// ---------------------------------------------------------------------------
__global__ void conv_w(const float* __restrict__ W,
                       __nv_bfloat16* __restrict__ hi,
                       __nv_bfloat16* __restrict__ lo)
{
    int k = blockIdx.x;
    int n = threadIdx.x;
    float w = W[k * 256 + n];
    __nv_bfloat16 h = __float2bfloat16(w);
    hi[n * 256 + k] = h;
    lo[n * 256 + k] = __float2bfloat16(w - __bfloat162float(h));
}

// ---------------------------------------------------------------------------
// Tensor-core GEMM via mma.sync m16n8k16 bf16, fp32 emulated as bf16x3.
// (unchanged from round 7 — known good, ~300us each)
// ---------------------------------------------------------------------------
#define GSM_AHI  0
#define GSM_ALO  18432
#define GSM_WHI  36864
#define GSM_WLO  55296
#define GSM_BIAS 73728
#define GEMM_SMEM 74240

#define MMA16816(d, a, b0, b1) \
    asm volatile( \
        "mma.sync.aligned.m16n8k16.row.col.f32.bf16.bf16.f32 " \
        "{%0,%1,%2,%3}, {%4,%5,%6,%7}, {%8,%9}, {%0,%1,%2,%3};" \
        : "+f"((d)[0]), "+f"((d)[1]), "+f"((d)[2]), "+f"((d)[3]) \
        : "r"((a)[0]), "r"((a)[1]), "r"((a)[2]), "r"((a)[3]), \
          "r"(b0), "r"(b1))

__global__ void __launch_bounds__(256) gemm_mma(
    const float* __restrict__ A,
    const __nv_bfloat16* __restrict__ Whi_g,
    const __nv_bfloat16* __restrict__ Wlo_g,
    const float* __restrict__ bias,
    float* __restrict__ C, int mode)
{
    extern __shared__ char sm[];
    __nv_bfloat16* sAhi = (__nv_bfloat16*)(sm + GSM_AHI);   // [128][72]
    __nv_bfloat16* sAlo = (__nv_bfloat16*)(sm + GSM_ALO);
    __nv_bfloat16* sWhi = (__nv_bfloat16*)(sm + GSM_WHI);   // [128][72]
    __nv_bfloat16* sWlo = (__nv_bfloat16*)(sm + GSM_WLO);
    float* sBias = (float*)(sm + GSM_BIAS);                  // [128]

    const int tid  = threadIdx.x;
    const int wid  = tid >> 5;
    const int lane = tid & 31;
    const int rowTile = blockIdx.y;
    const int colTile = blockIdx.x;

    const int wr = wid & 3;
    const int wc = wid >> 2;
    const int g   = lane >> 2;
    const int tig = lane & 3;

    const float* Ab = A + (size_t)rowTile * 128 * 256;

    if (tid < 128) sBias[tid] = bias[colTile * 128 + tid];

    float d[16][4];
#pragma unroll
    for (int i = 0; i < 16; i++)
#pragma unroll
        for (int q = 0; q < 4; q++) d[i][q] = 0.f;

    for (int kc = 0; kc < 4; kc++) {
        __syncthreads();

#pragma unroll
        for (int i = 0; i < 8; i++) {
            int lin = i * 256 + tid;
            int row = lin >> 4;
            int kv  = lin & 15;
            float4 v = *(const float4*)(Ab + (size_t)row * 256 + kc * 64 + kv * 4);
            __nv_bfloat16 h0 = __float2bfloat16(v.x);
            __nv_bfloat16 h1 = __float2bfloat16(v.y);
            __nv_bfloat16 h2 = __float2bfloat16(v.z);
            __nv_bfloat16 h3 = __float2bfloat16(v.w);
            __nv_bfloat16 l0 = __float2bfloat16(v.x - __bfloat162float(h0));
            __nv_bfloat16 l1 = __float2bfloat16(v.y - __bfloat162float(h1));
            __nv_bfloat16 l2 = __float2bfloat16(v.z - __bfloat162float(h2));
            __nv_bfloat16 l3 = __float2bfloat16(v.w - __bfloat162float(h3));
            int o = row * 72 + kv * 4;
            *(__nv_bfloat162*)(sAhi + o)     = __nv_bfloat162(h0, h1);
            *(__nv_bfloat162*)(sAhi + o + 2) = __nv_bfloat162(h2, h3);
            *(__nv_bfloat162*)(sAlo + o)     = __nv_bfloat162(l0, l1);
            *(__nv_bfloat162*)(sAlo + o + 2) = __nv_bfloat162(l2, l3);
        }

#pragma unroll
        for (int i = 0; i < 4; i++) {
            int lin = i * 256 + tid;
            int n  = lin >> 3;
            int k8 = lin & 7;
            size_t go = (size_t)(colTile * 128 + n) * 256 + kc * 64 + k8 * 8;
            uint4 vh = *(const uint4*)(Whi_g + go);
            uint4 vl = *(const uint4*)(Wlo_g + go);
            *(uint4*)(sWhi + n * 72 + k8 * 8) = vh;
            *(uint4*)(sWlo + n * 72 + k8 * 8) = vl;
        }
        __syncthreads();

#pragma unroll
        for (int ks = 0; ks < 4; ks++) {
            const int kb = ks * 16;
            uint32_t ahi[2][4], alo[2][4];
#pragma unroll
            for (int mt = 0; mt < 2; mt++) {
                int rb = wr * 32 + mt * 16;
                int o00 = (rb + g) * 72 + kb + 2 * tig;
                int o10 = (rb + g + 8) * 72 + kb + 2 * tig;
                ahi[mt][0] = *(const uint32_t*)(sAhi + o00);
                ahi[mt][1] = *(const uint32_t*)(sAhi + o10);
                ahi[mt][2] = *(const uint32_t*)(sAhi + o00 + 8);
                ahi[mt][3] = *(const uint32_t*)(sAhi + o10 + 8);
                alo[mt][0] = *(const uint32_t*)(sAlo + o00);
                alo[mt][1] = *(const uint32_t*)(sAlo + o10);
                alo[mt][2] = *(const uint32_t*)(sAlo + o00 + 8);
                alo[mt][3] = *(const uint32_t*)(sAlo + o10 + 8);
            }
#pragma unroll
            for (int nt = 0; nt < 8; nt++) {
                int cb = wc * 64 + nt * 8;
                int ob = (cb + g) * 72 + kb + 2 * tig;
                uint32_t bh0 = *(const uint32_t*)(sWhi + ob);
                uint32_t bh1 = *(const uint32_t*)(sWhi + ob + 8);
                uint32_t bl0 = *(const uint32_t*)(sWlo + ob);
                uint32_t bl1 = *(const uint32_t*)(sWlo + ob + 8);
#pragma unroll
                for (int mt = 0; mt < 2; mt++) {
                    MMA16816(d[mt * 8 + nt], ahi[mt], bh0, bh1);
                    MMA16816(d[mt * 8 + nt], ahi[mt], bl0, bl1);
                    MMA16816(d[mt * 8 + nt], alo[mt], bh0, bh1);
                }
            }
        }
    }

#pragma unroll
    for (int mt = 0; mt < 2; mt++) {
        long r0 = (long)rowTile * 128 + wr * 32 + mt * 16 + g;
        long r1 = r0 + 8;
        size_t off0, off1;
        if (mode == 0) {
            off0 = (size_t)r0 * 256;
            off1 = (size_t)r1 * 256;
        } else {
            off0 = ((size_t)(r0 % Tt_) * Bb_ + (r0 / Tt_)) * 256;
            off1 = ((size_t)(r1 % Tt_) * Bb_ + (r1 / Tt_)) * 256;
        }
#pragma unroll
        for (int nt = 0; nt < 8; nt++) {
            int lc  = wc * 64 + nt * 8 + 2 * tig;
            int gc  = colTile * 128 + lc;
            float b0 = sBias[lc], b1 = sBias[lc + 1];
            float* p0 = C + off0 + gc;
            float* p1 = C + off1 + gc;
            float2 v0 = make_float2(d[mt * 8 + nt][0] + b0, d[mt * 8 + nt][1] + b1);
            float2 v1 = make_float2(d[mt * 8 + nt][2] + b0, d[mt * 8 + nt][3] + b1);
            *(float2*)p0 = v0;
            *(float2*)p1 = v1;
        }
    }
}

// ---------------------------------------------------------------------------
// K-split cluster scan v2. 2 CTAs per chain. Role-split warps:
//   warps 4-7 (HI wid, issue priority) = senders: compute partials for the
//     PEER's 128 columns, b64-pack pairs via shfl, st.async to peer.
//   warps 0-3 = finalizers: compute partials for OWN columns, wait on the
//     peer's partials (tx mbarrier), fast-tanh, store h.
// Weights fully register-resident (64 pairs). Same buffer/parity protocol
// as round 5 (proven correct).
// ---------------------------------------------------------------------------
#define FMA2(acc, h, w) \
    asm("fma.rn.f32x2 %0, %1, %2, %0;" : "+l"(acc) : "l"(h), "l"(w))

__device__ __forceinline__ unsigned long long pack2(float lo, float hi) {
    unsigned long long v;
    asm("mov.b64 %0, {%1, %2};" : "=l"(v) : "f"(lo), "f"(hi));
    return v;
}
__device__ __forceinline__ float sum2(unsigned long long v) {
    float lo, hi;
    asm("mov.b64 {%0, %1}, %2;" : "=f"(lo), "=f"(hi) : "l"(v));
    return lo + hi;
}
__device__ __forceinline__ uint32_t mapa_u32(uint32_t laddr, uint32_t peer) {
    uint32_t r;
    asm("mapa.shared::cluster.u32 %0, %1, %2;" : "=r"(r) : "r"(laddr), "r"(peer));
    return r;
}
__device__ __forceinline__ void mbar_expect_tx(uint32_t addr, uint32_t bytes) {
    asm volatile("mbarrier.arrive.expect_tx.shared.b64 _, [%0], %1;"
                 :: "r"(addr), "r"(bytes) : "memory");
}
__device__ __forceinline__ void st_async_b64(uint32_t raddr, unsigned long long v,
                                             uint32_t rbar) {
    asm volatile(
        "st.async.shared::cluster.mbarrier::complete_tx::bytes.b64 [%0], %1, [%2];"
        :: "r"(raddr), "l"(v), "r"(rbar) : "memory");
}
__device__ __forceinline__ void mbar_wait_cluster(uint32_t addr, uint32_t parity) {
    asm volatile(
        "{\n\t"
        ".reg .pred P;\n\t"
        "WL%=:\n\t"
        "mbarrier.try_wait.parity.acquire.cluster.shared::cta.b64 P, [%0], %1, 0x989680;\n\t"
        "@P bra WD%=;\n\t"
        "bra WL%=;\n\t"
        "WD%=:\n\t"
        "}" :: "r"(addr), "r"(parity) : "memory");
}
// fast tanh: 1 - 2/(e^{2z}+1); saturates correctly at +/-inf
__device__ __forceinline__ float tanh_fast(float z) {
    float e = __expf(2.0f * z);
    return 1.0f - __fdividef(2.0f, e + 1.0f);
}

__global__ void __launch_bounds__(256, 1) __cluster_dims__(2, 1, 1)
rnn_scan_ksplit2(
    const float* __restrict__ xp,   // (T, B, H)
    const float* __restrict__ Whh,  // (H, H) [k][j]
    const float* __restrict__ h0,   // (B, H)
    float* __restrict__ hs,         // (B, T, H)
    float* __restrict__ hfin)       // (B, H)
{
    __shared__ float hbuf[2][128];                         // local h half
    __shared__ float rbuf[2][128];                         // received partials
    __shared__ __align__(8) unsigned long long bar[2];

    const int b    = blockIdx.x >> 1;
    const int r    = blockIdx.x & 1;
    const int tid  = threadIdx.x;
    const int wid  = tid >> 5;
    const int lane = tid & 31;
    const bool fin = (wid < 4);                            // finalizer role
    const int idx  = (wid & 3) * 32 + lane;                // 0..127 within role
    const int c    = fin ? (r * 128 + idx) : ((1 - r) * 128 + idx);
    const int kbase = r * 128;

    const uint32_t u_bar0 = smem_u32(&bar[0]);
    const uint32_t u_bar1 = smem_u32(&bar[1]);
    const uint32_t u_rbuf = smem_u32(&rbuf[0][0]);
    const uint32_t peer   = (uint32_t)(1 - r);
    const uint32_t ru_rbuf = mapa_u32(u_rbuf, peer);
    const uint32_t ru_bar0 = mapa_u32(u_bar0, peer);
    const uint32_t ru_bar1 = mapa_u32(u_bar1, peer);

    if (tid == 0) {
        mbar_init(u_bar0, 1);
        mbar_init(u_bar1, 1);
        mbar_expect_tx(u_bar0, 128 * 4);   // pre-arm t=0
        mbar_expect_tx(u_bar1, 128 * 4);   // pre-arm t=1
    }

    // 64 register-resident weight pairs: W_hh[kbase .. kbase+127][c]
    unsigned long long wr[64];
#pragma unroll
    for (int p = 0; p < 64; p++) {
        int k = kbase + 2 * p;
        wr[p] = pack2(Whh[(size_t)k * Hh_ + c], Whh[(size_t)(k + 1) * Hh_ + c]);
    }

    if (tid < 128) hbuf[0][tid] = h0[b * Hh_ + kbase + tid];
    __syncthreads();
    asm volatile("barrier.cluster.arrive.aligned;" ::: "memory");
    asm volatile("barrier.cluster.wait.aligned;"   ::: "memory");

    float xpc = 0.f, xpn = 0.f;
    if (fin) {
        xpc = __ldcs(&xp[((size_t)0 * Bb_ + b) * Hh_ + c]);
        xpn = __ldcs(&xp[((size_t)1 * Bb_ + b) * Hh_ + c]);
    }

    const size_t hs_base = ((size_t)b * Tt_) * Hh_ + c;
    float hlast = 0.f;

    for (int t = 0; t < Tt_; t++) {
        const int pb = t & 1;
        const int nb = pb ^ 1;

        // partial[c] over the local 128 k-rows (h broadcast from local smem)
        const ulonglong2* h2 = (const ulonglong2*)(&hbuf[pb][0]);
        unsigned long long a0 = 0ull, a1 = 0ull, a2 = 0ull, a3 = 0ull;
#pragma unroll
        for (int q = 0; q < 16; q++) {
            ulonglong2 hv0 = h2[2 * q];
            ulonglong2 hv1 = h2[2 * q + 1];
            FMA2(a0, hv0.x, wr[4 * q + 0]);
            FMA2(a1, hv0.y, wr[4 * q + 1]);
            FMA2(a2, hv1.x, wr[4 * q + 2]);
            FMA2(a3, hv1.y, wr[4 * q + 3]);
        }
        float part = (sum2(a0) + sum2(a1)) + (sum2(a2) + sum2(a3));

        if (!fin) {
            // pack adjacent-column partials into one b64 remote store
            float pHi = __shfl_down_sync(0xffffffffu, part, 1);
            if ((lane & 1) == 0) {
                uint32_t rb = (pb == 0) ? ru_bar0 : ru_bar1;
                st_async_b64(ru_rbuf + (uint32_t)(pb * 128 + idx) * 4u,
                             pack2(part, pHi), rb);
            }
        } else {
            uint32_t ub = (pb == 0) ? u_bar0 : u_bar1;
            mbar_wait_cluster(ub, (t >> 1) & 1);
            if (idx == 0 && t + 2 < Tt_) mbar_expect_tx(ub, 128 * 4);

            float h = tanh_fast(part + rbuf[pb][idx] + xpc);
            hs[hs_base + (size_t)t * Hh_] = h;
            hlast = h;
            hbuf[nb][idx] = h;

            xpc = xpn;
            if (t + 2 < Tt_)
                xpn = __ldcs(&xp[((size_t)(t + 2) * Bb_ + b) * Hh_ + c]);
        }
        __syncthreads();   // hbuf[nb] visible CTA-wide before next compute
    }

    if (fin) hfin[b * Hh_ + c] = hlast;

    asm volatile("barrier.cluster.arrive.aligned;" ::: "memory");
    asm volatile("barrier.cluster.wait.aligned;"   ::: "memory");
}

// ---------------------------------------------------------------------------
// Launch
// ---------------------------------------------------------------------------
extern "C" void kernel_launch(void* const* d_in, const int* in_sizes, int n_in,
                              void* d_out, int out_size)
{
    const float* x    = (const float*)d_in[0];  // (B,T,D)
    const float* h0   = (const float*)d_in[1];  // (B,H)
    const float* W_xh = (const float*)d_in[2];  // (D,H)
    const float* W_hh = (const float*)d_in[3];  // (H,H)
    const float* b_h  = (const float*)d_in[4];  // (H)
    const float* W_hy = (const float*)d_in[5];  // (H,O)
    const float* b_y  = (const float*)d_in[6];  // (O)

    float* out  = (float*)d_out;                           // (B,T,O)
    float* hfin = out + (size_t)Bb_ * Tt_ * Oo_;           // (B,H)

    void *xp_ptr, *hs_ptr, *wxh_hi, *wxh_lo, *why_hi, *why_lo;
    cudaGetSymbolAddress(&xp_ptr, g_xp);
    cudaGetSymbolAddress(&hs_ptr, g_hs);
    cudaGetSymbolAddress(&wxh_hi, g_wxh_hi);
    cudaGetSymbolAddress(&wxh_lo, g_wxh_lo);
    cudaGetSymbolAddress(&why_hi, g_why_hi);
    cudaGetSymbolAddress(&why_lo, g_why_lo);

    cudaFuncSetAttribute(gemm_mma,
                         cudaFuncAttributeMaxDynamicSharedMemorySize, GEMM_SMEM);

    // 0) split weights into bf16 hi/lo (transposed)
    conv_w<<<256, 256>>>(W_xh, (__nv_bfloat16*)wxh_hi, (__nv_bfloat16*)wxh_lo);
    conv_w<<<256, 256>>>(W_hy, (__nv_bfloat16*)why_hi, (__nv_bfloat16*)why_lo);

    const int M = Bb_ * Tt_;            // 262144 rows
    dim3 gemmGrid(2, M / 128);

    // 1) xp = x @ W_xh + b_h   -> (T,B,H)
    gemm_mma<<<gemmGrid, 256, GEMM_SMEM>>>(
        x, (const __nv_bfloat16*)wxh_hi, (const __nv_bfloat16*)wxh_lo,
        b_h, (float*)xp_ptr, 1);

    // 2) k-split cluster scan v2 -> hs (B,T,H), h_final
    rnn_scan_ksplit2<<<2 * Bb_, 256>>>((const float*)xp_ptr, W_hh, h0,
                                       (float*)hs_ptr, hfin);

    // 3) out = hs @ W_hy + b_y -> (B,T,O)
    gemm_mma<<<gemmGrid, 256, GEMM_SMEM>>>(
        (const float*)hs_ptr, (const __nv_bfloat16*)why_hi,
        (const __nv_bfloat16*)why_lo, b_y, out, 0);
}